// round 10
// baseline (speedup 1.0000x reference)
#include <cuda_runtime.h>

// QuantizedAdd via per-block float shared-memory LUTs.
// gx=28 -> exactly 7 int4-iterations per thread (50176 = 28*256*7), software-
// pipelined by 1 iteration (prefetch next loads before current store) to keep
// 4 LDG.128 outstanding continuously. 43% fewer blocks than R8 amortizes LUT
// builds. Output buffer float32; bit-exact (fp32 sums of small ints).

#define THREADS 256
#define ITERS 7

__device__ __forceinline__ int rq(int x, int z, int lsh, int M0,
                                  unsigned mask, int thr_base, int rsh)
{
    int d = (x - z) << lsh;
    long long nudge = (d >= 0) ? (1LL << 30) : (1LL - (1LL << 30));
    long long prod = (long long)d * (long long)M0 + nudge;   // IMAD.WIDE
    int v = (int)(prod >> 31);                               // |v| <= 1020
    unsigned rem = (unsigned)v & mask;
    unsigned thr = (unsigned)(thr_base + (v < 0 ? 1 : 0));
    return (v >> rsh) + (rem > thr ? 1 : 0);
}

__device__ __forceinline__ void build_luts(
    int b, int t,
    const int* __restrict__ batch_cluster,
    const int* __restrict__ z_bypass, const int* __restrict__ z_prev,
    const int* __restrict__ z3_arr,
    const int* __restrict__ M0_bypass, const int* __restrict__ M0_prev,
    const int* __restrict__ shift_bypass, const int* __restrict__ shift_prev,
    float* lut1, float* lut2)
{
    const int c  = __ldg(&batch_cluster[b]);
    const int z1 = __ldg(&z_bypass[c]);
    const int z2 = __ldg(&z_prev[c]);
    const int z3 = __ldg(&z3_arr[c]);
    const int M1 = __ldg(&M0_bypass[c]);
    const int M2 = __ldg(&M0_prev[c]);
    const int s1 = __ldg(&shift_bypass[c]);
    const int s2 = __ldg(&shift_prev[c]);

    const int lsh1 = s1 < 0 ? -s1 : 0;
    const int rsh1 = s1 < 0 ? 0 : s1;
    const int lsh2 = s2 < 0 ? -s2 : 0;
    const int rsh2 = s2 < 0 ? 0 : s2;
    const unsigned mask1 = (1u << rsh1) - 1u;
    const unsigned mask2 = (1u << rsh2) - 1u;

    lut1[t] = (float)(rq(t, z1, lsh1, M1, mask1, (int)(mask1 >> 1), rsh1) + z3);
    lut2[t] = (float)(rq(t, z2, lsh2, M2, mask2, (int)(mask2 >> 1), rsh2));
}

__device__ __forceinline__ float4 apply_lut(const float* lut1, const float* lut2,
                                            int4 xb, int4 xp)
{
    float4 o;
    o.x = fmaxf(-128.f, fminf(127.f, lut1[xb.x] + lut2[xp.x]));
    o.y = fmaxf(-128.f, fminf(127.f, lut1[xb.y] + lut2[xp.y]));
    o.z = fmaxf(-128.f, fminf(127.f, lut1[xb.z] + lut2[xp.z]));
    o.w = fmaxf(-128.f, fminf(127.f, lut1[xb.w] + lut2[xp.w]));
    return o;
}

template <bool EXACT>
__global__ void __launch_bounds__(THREADS)
qadd_kernel(const int4* __restrict__ bypass,
            const int4* __restrict__ prev,
            const int* __restrict__ batch_cluster,
            const int* __restrict__ z_bypass,
            const int* __restrict__ z_prev,
            const int* __restrict__ z3_arr,
            const int* __restrict__ M0_bypass,
            const int* __restrict__ M0_prev,
            const int* __restrict__ shift_bypass,
            const int* __restrict__ shift_prev,
            float4* __restrict__ out,
            int nv4)   // (C*H*W)/4 per sample
{
    __shared__ float lut1[256];
    __shared__ float lut2[256];

    const int b = blockIdx.y;
    const int t = threadIdx.x;

    build_luts(b, t, batch_cluster, z_bypass, z_prev, z3_arr,
               M0_bypass, M0_prev, shift_bypass, shift_prev, lut1, lut2);
    __syncthreads();

    const size_t sbase = (size_t)b * (size_t)nv4;
    const int stride = gridDim.x * THREADS;
    const int i0 = blockIdx.x * THREADS + t;

    if (EXACT) {
        // exactly ITERS iterations per thread, software-pipelined by 1:
        // loads for k+1 are issued before the store for k.
        int4 xb = bypass[sbase + i0];
        int4 xp = prev  [sbase + i0];
        #pragma unroll
        for (int k = 0; k < ITERS - 1; k++) {
            const size_t inext = sbase + i0 + (size_t)(k + 1) * stride;
            int4 xbn = bypass[inext];
            int4 xpn = prev  [inext];
            out[sbase + i0 + (size_t)k * stride] = apply_lut(lut1, lut2, xb, xp);
            xb = xbn;
            xp = xpn;
        }
        out[sbase + i0 + (size_t)(ITERS - 1) * stride] = apply_lut(lut1, lut2, xb, xp);
    } else {
        for (int i = i0; i < nv4; i += stride) {
            const int4 xb = bypass[sbase + i];
            const int4 xp = prev[sbase + i];
            out[sbase + i] = apply_lut(lut1, lut2, xb, xp);
        }
    }
}

extern "C" void kernel_launch(void* const* d_in, const int* in_sizes, int n_in,
                              void* d_out, int out_size)
{
    // ---- resolve input mapping from sizes (host-only) ----
    int bigIdx[2] = {0, 1};  int nbig = 0;
    int smallIdx[8] = {0,0,0,0,0,0,0,0}; int nsmall = 0;
    int bcIdx = 2;

    for (int i = 0; i < n_in; i++) {
        if (in_sizes[i] > 100000) {
            if (nbig < 2) bigIdx[nbig] = i;
            nbig++;
        } else if (in_sizes[i] <= 64) {
            if (nsmall < 8) smallIdx[nsmall++] = i;
        } else {
            bcIdx = i;
        }
    }

    const int4* bypass = (const int4*)d_in[bigIdx[0]];
    const int4* prev   = (const int4*)d_in[bigIdx[1]];
    const int*  bc     = (const int*)d_in[bcIdx];

    const int *z1, *z2, *z3, *M1, *M2, *s1, *s2;
    if (in_sizes[0] > 100000) {
        // dict order: z_bypass, z_prev, z3, M0_bypass, M0_prev, shift_bypass, shift_prev
        z1 = (const int*)d_in[smallIdx[0]];
        z2 = (const int*)d_in[smallIdx[1]];
        z3 = (const int*)d_in[smallIdx[2]];
        M1 = (const int*)d_in[smallIdx[3]];
        M2 = (const int*)d_in[smallIdx[4]];
        s1 = (const int*)d_in[smallIdx[5]];
        s2 = (const int*)d_in[smallIdx[6]];
    } else {
        // alphabetical: M0_bypass, M0_prev, shift_bypass, shift_prev, z3, z_bypass, z_prev
        M1 = (const int*)d_in[smallIdx[0]];
        M2 = (const int*)d_in[smallIdx[1]];
        s1 = (const int*)d_in[smallIdx[2]];
        s2 = (const int*)d_in[smallIdx[3]];
        z3 = (const int*)d_in[smallIdx[4]];
        z1 = (const int*)d_in[smallIdx[5]];
        z2 = (const int*)d_in[smallIdx[6]];
    }

    const int B   = in_sizes[bcIdx];               // 128
    const int chw = in_sizes[bigIdx[0]] / B;       // 200704
    const int nv4 = chw / 4;                       // 50176 = 28*256*7

    int gx = (nv4 + THREADS * ITERS - 1) / (THREADS * ITERS);   // 28
    dim3 grid(gx, B);

    if (gx * THREADS * ITERS == nv4) {
        qadd_kernel<true><<<grid, THREADS>>>(bypass, prev, bc, z1, z2, z3,
                                             M1, M2, s1, s2,
                                             (float4*)d_out, nv4);
    } else {
        qadd_kernel<false><<<grid, THREADS>>>(bypass, prev, bc, z1, z2, z3,
                                              M1, M2, s1, s2,
                                              (float4*)d_out, nv4);
    }
}